// round 2
// baseline (speedup 1.0000x reference)
#include <cuda_runtime.h>
#include <math.h>
#include <stddef.h>

// ---------------------------------------------------------------------------
// biSoftmax: out[h] = ((A1@W1^T - A2@W2^T)^2) @ V[h]
//   where A_i = softmax( (X[h]@Wqi^T) @ (X[h]@Wki^T)^T / sqrt(S) )
//   and Q/K/V projections share weights across heads.
// H=8, S=2048, D=2048.  All fp32.
// ---------------------------------------------------------------------------

#define SEQ 2048
#define NH 8
#define MROWS (NH * SEQ)               // 16384
#define SS ((size_t)SEQ * SEQ)         // per-head matrix elements

// Scratch (device globals; allocation-free). 7 buffers x 128 MiB.
__device__ float g_Q1[(size_t)MROWS * SEQ];
__device__ float g_K1[(size_t)MROWS * SEQ];
__device__ float g_Q2[(size_t)MROWS * SEQ];
__device__ float g_K2[(size_t)MROWS * SEQ];
__device__ float g_V [(size_t)MROWS * SEQ];
__device__ float g_S1[(size_t)MROWS * SEQ];
__device__ float g_S2[(size_t)MROWS * SEQ];

// ---------------------------------------------------------------------------
// Tiled fp32 GEMM.
//   BT = true : C = alpha * A @ B^T   (A: [M,K] rm, B: [N,K] rm)
//   BT = false: C = alpha * A @ B     (A: [M,K] rm, B: [K,N] rm)
// blockIdx.z batches with strides sA/sB/sC (elements).
// Requires M%128==0, N%128==0, K%16==0 (true for all shapes here).
// ---------------------------------------------------------------------------
constexpr int BM = 128, BN = 128, BK = 16;

template <bool BT>
__global__ __launch_bounds__(256, 1)
void gemm_kernel(const float* __restrict__ A, const float* __restrict__ B,
                 float* __restrict__ C,
                 int M, int N, int K,
                 size_t sA, size_t sB, size_t sC, float alpha)
{
    __shared__ float As[BK][BM + 4];
    __shared__ float Bs[BK][BN + 4];

    const int tid = threadIdx.x;
    const int tx = tid & 15;       // 0..15  -> col fragment
    const int ty = tid >> 4;       // 0..15  -> row fragment

    const int row0 = blockIdx.y * BM;
    const int col0 = blockIdx.x * BN;

    const float* Ag = A + blockIdx.z * sA + (size_t)row0 * K;
    const float* Bg = BT ? (B + blockIdx.z * sB + (size_t)col0 * K)
                         : (B + blockIdx.z * sB + col0);
    float* Cg = C + blockIdx.z * sC + (size_t)row0 * N + col0;

    float acc[8][8];
    #pragma unroll
    for (int i = 0; i < 8; i++)
        #pragma unroll
        for (int j = 0; j < 8; j++) acc[i][j] = 0.0f;

    // loader indices
    const int ar = tid >> 2;          // 0..63 (rows ar, ar+64)
    const int ac = (tid & 3) * 4;     // 0,4,8,12
    const int br = tid >> 5;          // 0..7  (rows br, br+8)  [NN path]
    const int bc = (tid & 31) * 4;    // 0..124                 [NN path]

    for (int kt = 0; kt < K; kt += BK) {
        // ---- load A tile (transposed into smem) ----
        float4 a0 = *(const float4*)(Ag + (size_t)ar * K + kt + ac);
        float4 a1 = *(const float4*)(Ag + (size_t)(ar + 64) * K + kt + ac);
        As[ac + 0][ar] = a0.x; As[ac + 1][ar] = a0.y;
        As[ac + 2][ar] = a0.z; As[ac + 3][ar] = a0.w;
        As[ac + 0][ar + 64] = a1.x; As[ac + 1][ar + 64] = a1.y;
        As[ac + 2][ar + 64] = a1.z; As[ac + 3][ar + 64] = a1.w;

        // ---- load B tile ----
        if (BT) {
            float4 b0 = *(const float4*)(Bg + (size_t)ar * K + kt + ac);
            float4 b1 = *(const float4*)(Bg + (size_t)(ar + 64) * K + kt + ac);
            Bs[ac + 0][ar] = b0.x; Bs[ac + 1][ar] = b0.y;
            Bs[ac + 2][ar] = b0.z; Bs[ac + 3][ar] = b0.w;
            Bs[ac + 0][ar + 64] = b1.x; Bs[ac + 1][ar + 64] = b1.y;
            Bs[ac + 2][ar + 64] = b1.z; Bs[ac + 3][ar + 64] = b1.w;
        } else {
            float4 b0 = *(const float4*)(Bg + (size_t)(kt + br) * N + bc);
            float4 b1 = *(const float4*)(Bg + (size_t)(kt + br + 8) * N + bc);
            *(float4*)&Bs[br][bc]     = b0;
            *(float4*)&Bs[br + 8][bc] = b1;
        }
        __syncthreads();

        // ---- FMA on the tile ----
        #pragma unroll
        for (int k = 0; k < BK; k++) {
            float a[8], b[8];
            #pragma unroll
            for (int i = 0; i < 8; i++) a[i] = As[k][ty * 8 + i];
            #pragma unroll
            for (int j = 0; j < 8; j++) b[j] = Bs[k][tx * 8 + j];
            #pragma unroll
            for (int i = 0; i < 8; i++)
                #pragma unroll
                for (int j = 0; j < 8; j++)
                    acc[i][j] = fmaf(a[i], b[j], acc[i][j]);
        }
        __syncthreads();
    }

    // ---- epilogue ----
    #pragma unroll
    for (int i = 0; i < 8; i++) {
        float* crow = Cg + (size_t)(ty * 8 + i) * N + tx * 8;
        float4 v0, v1;
        v0.x = acc[i][0] * alpha; v0.y = acc[i][1] * alpha;
        v0.z = acc[i][2] * alpha; v0.w = acc[i][3] * alpha;
        v1.x = acc[i][4] * alpha; v1.y = acc[i][5] * alpha;
        v1.z = acc[i][6] * alpha; v1.w = acc[i][7] * alpha;
        *(float4*)(crow)     = v0;
        *(float4*)(crow + 4) = v1;
    }
}

// ---------------------------------------------------------------------------
// Row softmax over SEQ columns, in place. One block per row.
// ---------------------------------------------------------------------------
__global__ __launch_bounds__(256)
void softmax_rows(float* __restrict__ data)
{
    const int tid = threadIdx.x;
    float* p = data + (size_t)blockIdx.x * SEQ;
    __shared__ float red[256];

    float m = -INFINITY;
    for (int i = tid; i < SEQ; i += 256) m = fmaxf(m, p[i]);
    red[tid] = m;
    __syncthreads();
    for (int s = 128; s > 0; s >>= 1) {
        if (tid < s) red[tid] = fmaxf(red[tid], red[tid + s]);
        __syncthreads();
    }
    m = red[0];
    __syncthreads();

    float sum = 0.0f;
    for (int i = tid; i < SEQ; i += 256) {
        float e = expf(p[i] - m);
        p[i] = e;
        sum += e;
    }
    red[tid] = sum;
    __syncthreads();
    for (int s = 128; s > 0; s >>= 1) {
        if (tid < s) red[tid] += red[tid + s];
        __syncthreads();
    }
    const float inv = 1.0f / red[0];
    __syncthreads();
    for (int i = tid; i < SEQ; i += 256) p[i] *= inv;
}

// ---------------------------------------------------------------------------
// circle = (a - b)^2, written into a (in place on a's buffer)
// ---------------------------------------------------------------------------
__global__ __launch_bounds__(256)
void diffsq_kernel(float* __restrict__ a, const float* __restrict__ b, size_t n)
{
    size_t i = (size_t)blockIdx.x * blockDim.x + threadIdx.x;
    size_t stride = (size_t)gridDim.x * blockDim.x;
    for (; i < n; i += stride) {
        float d = a[i] - b[i];
        a[i] = d * d;
    }
}

// ---------------------------------------------------------------------------
extern "C" void kernel_launch(void* const* d_in, const int* in_sizes, int n_in,
                              void* d_out, int out_size)
{
    (void)in_sizes; (void)n_in; (void)out_size;
    const float* x   = (const float*)d_in[0];
    const float* Wq1 = (const float*)d_in[1];
    const float* Wk1 = (const float*)d_in[2];
    const float* Wq2 = (const float*)d_in[3];
    const float* Wk2 = (const float*)d_in[4];
    const float* Wv  = (const float*)d_in[5];
    const float* W1  = (const float*)d_in[6];
    const float* W2  = (const float*)d_in[7];
    float* out = (float*)d_out;

    float *Q1, *K1, *Q2, *K2, *V, *S1, *S2;
    cudaGetSymbolAddress((void**)&Q1, g_Q1);
    cudaGetSymbolAddress((void**)&K1, g_K1);
    cudaGetSymbolAddress((void**)&Q2, g_Q2);
    cudaGetSymbolAddress((void**)&K2, g_K2);
    cudaGetSymbolAddress((void**)&V,  g_V);
    cudaGetSymbolAddress((void**)&S1, g_S1);
    cudaGetSymbolAddress((void**)&S2, g_S2);

    const float scale = 1.0f / sqrtf((float)SEQ);

    dim3 blk(256);
    dim3 gproj(SEQ / BN, MROWS / BM, 1);   // 16 x 128
    dim3 ghead(SEQ / BN, SEQ / BM, NH);    // 16 x 16 x 8

    // 1) shared-weight projections: P = X @ W^T   [16384 x 2048]
    gemm_kernel<true><<<gproj, blk>>>(x, Wq1, Q1, MROWS, SEQ, SEQ, 0, 0, 0, 1.0f);
    gemm_kernel<true><<<gproj, blk>>>(x, Wk1, K1, MROWS, SEQ, SEQ, 0, 0, 0, 1.0f);
    gemm_kernel<true><<<gproj, blk>>>(x, Wq2, Q2, MROWS, SEQ, SEQ, 0, 0, 0, 1.0f);
    gemm_kernel<true><<<gproj, blk>>>(x, Wk2, K2, MROWS, SEQ, SEQ, 0, 0, 0, 1.0f);
    gemm_kernel<true><<<gproj, blk>>>(x, Wv,  V,  MROWS, SEQ, SEQ, 0, 0, 0, 1.0f);

    // 2) logits: S_i[h] = scale * Q_i[h] @ K_i[h]^T
    gemm_kernel<true><<<ghead, blk>>>(Q1, K1, S1, SEQ, SEQ, SEQ, SS, SS, SS, scale);
    gemm_kernel<true><<<ghead, blk>>>(Q2, K2, S2, SEQ, SEQ, SEQ, SS, SS, SS, scale);

    // 3) row softmax in place
    softmax_rows<<<MROWS, blk>>>(S1);
    softmax_rows<<<MROWS, blk>>>(S2);

    // 4) score GEMMs: score1 -> K1 (reuse), score2 -> Q1 (reuse)
    gemm_kernel<true><<<ghead, blk>>>(S1, W1, K1, SEQ, SEQ, SEQ, SS, 0, SS, 1.0f);
    gemm_kernel<true><<<ghead, blk>>>(S2, W2, Q1, SEQ, SEQ, SEQ, SS, 0, SS, 1.0f);

    // 5) circle = (score1 - score2)^2  -> K1 in place
    diffsq_kernel<<<4096, blk>>>(K1, Q1, (size_t)MROWS * SEQ);

    // 6) out[h] = circle[h] @ V[h]   (NN)
    gemm_kernel<false><<<ghead, blk>>>(K1, V, out, SEQ, SEQ, SEQ, SS, SS, SS, 1.0f);
}

// round 4
// speedup vs baseline: 1.6334x; 1.6334x over previous
#include <cuda_runtime.h>
#include <cuda_bf16.h>
#include <math.h>
#include <stdint.h>
#include <stddef.h>

// ============================================================================
// biSoftmax on GB300 via HMMA (mma.sync bf16) split-precision GEMMs.
// (tcgen05/TMA PTX is rejected by the harness's family-level .target sm_103,
//  so we use mma.sync.m16n8k16.bf16 + cp.async + ldmatrix, all family-legal.)
// All GEMMs are NT: C[m,n] = alpha * sum_k A[m,k] * B[n,k]
// fp32 operands stored as bf16 (hi,lo); accumulate Ahi*Bhi + Ahi*Blo + Alo*Bhi
// in fp32 register accumulators (~2^-16 effective input precision).
// ============================================================================

#define SEQ 2048
#define NH 8
#define MROWS (NH * SEQ)                 // 16384
#define SSZ ((size_t)SEQ * SEQ)

typedef __nv_bfloat16 bf16;

// ---------------- scratch (device globals, allocation-free) ----------------
__device__ bf16 g_xh[(size_t)MROWS * SEQ],  g_xl[(size_t)MROWS * SEQ];
__device__ bf16 g_Wh[7 * SSZ],              g_Wl[7 * SSZ];   // Wq1,Wk1,Wq2,Wk2,Wv,W1,W2
__device__ bf16 g_Q1h[(size_t)MROWS * SEQ], g_Q1l[(size_t)MROWS * SEQ];
__device__ bf16 g_K1h[(size_t)MROWS * SEQ], g_K1l[(size_t)MROWS * SEQ];
__device__ bf16 g_Q2h[(size_t)MROWS * SEQ], g_Q2l[(size_t)MROWS * SEQ];
__device__ bf16 g_K2h[(size_t)MROWS * SEQ], g_K2l[(size_t)MROWS * SEQ];
__device__ bf16 g_Vth[(size_t)MROWS * SEQ], g_Vtl[(size_t)MROWS * SEQ];   // [h][e][t]
__device__ bf16 g_A1h[(size_t)MROWS * SEQ], g_A1l[(size_t)MROWS * SEQ];
__device__ bf16 g_A2h[(size_t)MROWS * SEQ], g_A2l[(size_t)MROWS * SEQ];
__device__ bf16 g_Ch [(size_t)MROWS * SEQ], g_Cl [(size_t)MROWS * SEQ];
__device__ float g_S1[(size_t)MROWS * SEQ], g_S2[(size_t)MROWS * SEQ];

// ---------------- PTX helpers (all family-target legal) ----------------
__device__ __forceinline__ uint32_t smem_u32(const void* p) {
    uint32_t a;
    asm("{ .reg .u64 t; cvta.to.shared.u64 t, %1; cvt.u32.u64 %0, t; }" : "=r"(a) : "l"(p));
    return a;
}

#define CP16(dst, src) \
    asm volatile("cp.async.cg.shared.global [%0], [%1], 16;" :: "r"(dst), "l"(src) : "memory")
#define CP_COMMIT() asm volatile("cp.async.commit_group;" ::: "memory")
#define CP_WAIT2()  asm volatile("cp.async.wait_group 2;" ::: "memory")

#define LDSM4(r0, r1, r2, r3, a) \
    asm volatile("ldmatrix.sync.aligned.m8n8.x4.shared.b16 {%0,%1,%2,%3}, [%4];" \
        : "=r"(r0), "=r"(r1), "=r"(r2), "=r"(r3) : "r"(a))

#define MMA_BF16(d, a, b) \
    asm volatile("mma.sync.aligned.m16n8k16.row.col.f32.bf16.bf16.f32 " \
        "{%0,%1,%2,%3}, {%4,%5,%6,%7}, {%8,%9}, {%0,%1,%2,%3};" \
        : "+f"((d)[0]), "+f"((d)[1]), "+f"((d)[2]), "+f"((d)[3]) \
        : "r"((a)[0]), "r"((a)[1]), "r"((a)[2]), "r"((a)[3]), "r"((b)[0]), "r"((b)[1]))

// ---------------- HMMA split-precision GEMM ----------------
// CTA tile 128x128, BK=32, 4 stages. smem row = 32 bf16 (64B) + 16B pad = 80B.
// Stage layout: Ahi[0,10240) Alo[10240,20480) Bhi[20480,30720) Blo[30720,40960)
static constexpr int STAGE_B = 40960;
static constexpr int SMEM_HG = 4 * STAGE_B;   // 163840

// EPI: 0 = fp32 * alpha, 1 = bf16 (hi,lo) pair
template <int EPI>
__global__ __launch_bounds__(256, 1)
void hgemm3(const bf16* __restrict__ Ah, const bf16* __restrict__ Al,
            const bf16* __restrict__ Bh, const bf16* __restrict__ Bl,
            float* __restrict__ Cf, bf16* __restrict__ Ch, bf16* __restrict__ Cl,
            int K, int ldc, size_t sC, int azRows, int bzRows, float alpha)
{
    extern __shared__ char smem[];
    const uint32_t sbase = smem_u32(smem);
    const int tid  = threadIdx.x;
    const int lane = tid & 31;
    const int wid  = tid >> 5;
    const int wm   = wid >> 2;          // 0..1  -> 64-row slab
    const int wn   = wid & 3;           // 0..3  -> 32-col slab
    const int row0 = blockIdx.y * 128;
    const int col0 = blockIdx.x * 128;
    const int z    = blockIdx.z;

    // ---- loader lanes: 256 threads, each 2x16B per buffer per stage ----
    const int lr  = tid >> 1;           // 0..127 row
    const int lcb = (tid & 1) * 2;      // chunk 0 or 2
    const size_t arow = (size_t)(row0 + z * azRows + lr);
    const size_t brow = (size_t)(col0 + z * bzRows + lr);
    const bf16* pAh = Ah + arow * K + lcb * 8;
    const bf16* pAl = Al + arow * K + lcb * 8;
    const bf16* pBh = Bh + brow * K + lcb * 8;
    const bf16* pBl = Bl + brow * K + lcb * 8;
    const uint32_t lsw = (uint32_t)(lr & 3);
    const uint32_t st1 = lr * 80 + (((uint32_t)lcb ^ lsw) << 4);
    const uint32_t st2 = lr * 80 + ((((uint32_t)lcb + 1u) ^ lsw) << 4);

    auto prefetch = [&](int kt) {
        const uint32_t sb = sbase + (uint32_t)(kt & 3) * STAGE_B;
        const int go = kt * 32;
        CP16(sb +          st1, pAh + go); CP16(sb +          st2, pAh + go + 8);
        CP16(sb + 10240u + st1, pAl + go); CP16(sb + 10240u + st2, pAl + go + 8);
        CP16(sb + 20480u + st1, pBh + go); CP16(sb + 20480u + st2, pBh + go + 8);
        CP16(sb + 30720u + st1, pBl + go); CP16(sb + 30720u + st2, pBl + go + 8);
    };

    // ---- fragment addressing ----
    const int lr16  = lane & 15;
    const uint32_t khalf = (uint32_t)(lane >> 4);
    const uint32_t fsw   = (uint32_t)(lane & 3);
    uint32_t a_base[4], b_base[2];
    #pragma unroll
    for (int mi = 0; mi < 4; mi++) a_base[mi] = (uint32_t)(wm * 64 + mi * 16 + lr16) * 80u;
    #pragma unroll
    for (int g = 0; g < 2; g++)    b_base[g]  = (uint32_t)(wn * 32 + g * 16 + lr16) * 80u;

    float acc[4][4][4];
    #pragma unroll
    for (int mi = 0; mi < 4; mi++)
        #pragma unroll
        for (int nj = 0; nj < 4; nj++)
            #pragma unroll
            for (int q = 0; q < 4; q++) acc[mi][nj][q] = 0.0f;

    const int nk = K >> 5;

    prefetch(0); CP_COMMIT();
    prefetch(1); CP_COMMIT();
    prefetch(2); CP_COMMIT();

    for (int kt = 0; kt < nk; kt++) {
        CP_WAIT2();
        __syncthreads();
        if (kt + 3 < nk) prefetch(kt + 3);
        CP_COMMIT();

        const uint32_t stg = sbase + (uint32_t)(kt & 3) * STAGE_B;
        #pragma unroll
        for (int ks = 0; ks < 2; ks++) {
            const uint32_t coff = ((((uint32_t)(ks * 2) + khalf) ^ fsw) << 4);
            uint32_t Ahi[4][4], Alo[4][4], Bhi[4][2], Blo[4][2];
            #pragma unroll
            for (int mi = 0; mi < 4; mi++) {
                LDSM4(Ahi[mi][0], Ahi[mi][1], Ahi[mi][2], Ahi[mi][3],
                      stg + a_base[mi] + coff);
                LDSM4(Alo[mi][0], Alo[mi][1], Alo[mi][2], Alo[mi][3],
                      stg + 10240u + a_base[mi] + coff);
            }
            #pragma unroll
            for (int g = 0; g < 2; g++) {
                uint32_t q0, q1, q2, q3;
                LDSM4(q0, q1, q2, q3, stg + 20480u + b_base[g] + coff);
                Bhi[2 * g][0] = q0; Bhi[2 * g][1] = q2;
                Bhi[2 * g + 1][0] = q1; Bhi[2 * g + 1][1] = q3;
                LDSM4(q0, q1, q2, q3, stg + 30720u + b_base[g] + coff);
                Blo[2 * g][0] = q0; Blo[2 * g][1] = q2;
                Blo[2 * g + 1][0] = q1; Blo[2 * g + 1][1] = q3;
            }
            #pragma unroll
            for (int mi = 0; mi < 4; mi++)
                #pragma unroll
                for (int nj = 0; nj < 4; nj++)
                    MMA_BF16(acc[mi][nj], Ahi[mi], Bhi[nj]);
            #pragma unroll
            for (int mi = 0; mi < 4; mi++)
                #pragma unroll
                for (int nj = 0; nj < 4; nj++)
                    MMA_BF16(acc[mi][nj], Ahi[mi], Blo[nj]);
            #pragma unroll
            for (int mi = 0; mi < 4; mi++)
                #pragma unroll
                for (int nj = 0; nj < 4; nj++)
                    MMA_BF16(acc[mi][nj], Alo[mi], Bhi[nj]);
        }
    }

    // ---- epilogue ----
    const size_t cb = (size_t)z * sC;
    #pragma unroll
    for (int mi = 0; mi < 4; mi++) {
        #pragma unroll
        for (int nj = 0; nj < 4; nj++) {
            const int rg = row0 + wm * 64 + mi * 16 + (lane >> 2);
            const int cg = col0 + wn * 32 + nj * 8 + (lane & 3) * 2;
            float d0 = acc[mi][nj][0] * alpha, d1 = acc[mi][nj][1] * alpha;
            float d2 = acc[mi][nj][2] * alpha, d3 = acc[mi][nj][3] * alpha;
            const size_t i0 = cb + (size_t)rg * ldc + cg;
            const size_t i1 = cb + (size_t)(rg + 8) * ldc + cg;
            if (EPI == 0) {
                *(float2*)(Cf + i0) = make_float2(d0, d1);
                *(float2*)(Cf + i1) = make_float2(d2, d3);
            } else {
                __nv_bfloat162 h, l;
                h.x = __float2bfloat16(d0);
                h.y = __float2bfloat16(d1);
                l.x = __float2bfloat16(d0 - __bfloat162float(h.x));
                l.y = __float2bfloat16(d1 - __bfloat162float(h.y));
                *(__nv_bfloat162*)(Ch + i0) = h;
                *(__nv_bfloat162*)(Cl + i0) = l;
                h.x = __float2bfloat16(d2);
                h.y = __float2bfloat16(d3);
                l.x = __float2bfloat16(d2 - __bfloat162float(h.x));
                l.y = __float2bfloat16(d3 - __bfloat162float(h.y));
                *(__nv_bfloat162*)(Ch + i1) = h;
                *(__nv_bfloat162*)(Cl + i1) = l;
            }
        }
    }
}

// ---------------- elementwise / softmax kernels ----------------
__global__ __launch_bounds__(256)
void f32_to_pair(const float* __restrict__ in, bf16* __restrict__ hi,
                 bf16* __restrict__ lo, size_t n)
{
    size_t i = (size_t)blockIdx.x * blockDim.x + threadIdx.x;
    size_t st = (size_t)gridDim.x * blockDim.x;
    for (; i < n; i += st) {
        float f = in[i];
        bf16 h = __float2bfloat16(f);
        hi[i] = h;
        lo[i] = __float2bfloat16(f - __bfloat162float(h));
    }
}

__global__ __launch_bounds__(256)
void softmax_pair(const float* __restrict__ S, bf16* __restrict__ Ph,
                  bf16* __restrict__ Pl)
{
    const int tid = threadIdx.x;
    const float* p = S + (size_t)blockIdx.x * SEQ;
    bf16* oh = Ph + (size_t)blockIdx.x * SEQ;
    bf16* ol = Pl + (size_t)blockIdx.x * SEQ;
    __shared__ float buf[SEQ];
    __shared__ float red[256];

    float m = -INFINITY;
    for (int i = tid; i < SEQ; i += 256) { float v = p[i]; buf[i] = v; m = fmaxf(m, v); }
    red[tid] = m; __syncthreads();
    for (int s = 128; s > 0; s >>= 1) { if (tid < s) red[tid] = fmaxf(red[tid], red[tid + s]); __syncthreads(); }
    m = red[0]; __syncthreads();

    float sum = 0.0f;
    for (int i = tid; i < SEQ; i += 256) { float e = __expf(buf[i] - m); buf[i] = e; sum += e; }
    red[tid] = sum; __syncthreads();
    for (int s = 128; s > 0; s >>= 1) { if (tid < s) red[tid] += red[tid + s]; __syncthreads(); }
    const float inv = 1.0f / red[0]; __syncthreads();

    for (int i = tid; i < SEQ; i += 256) {
        float f = buf[i] * inv;
        bf16 h = __float2bfloat16(f);
        oh[i] = h;
        ol[i] = __float2bfloat16(f - __bfloat162float(h));
    }
}

__global__ __launch_bounds__(256)
void diffsq_pair(const float* __restrict__ a, const float* __restrict__ b,
                 bf16* __restrict__ hi, bf16* __restrict__ lo, size_t n)
{
    size_t i = (size_t)blockIdx.x * blockDim.x + threadIdx.x;
    size_t st = (size_t)gridDim.x * blockDim.x;
    for (; i < n; i += st) {
        float d = a[i] - b[i];
        float f = d * d;
        bf16 h = __float2bfloat16(f);
        hi[i] = h;
        lo[i] = __float2bfloat16(f - __bfloat162float(h));
    }
}

// ---------------- host side ----------------
template <typename T>
static T* sym_addr(T* symbol) {
    void* p = nullptr;
    cudaGetSymbolAddress(&p, (const void*)symbol);
    return (T*)p;
}

static void run_hgemm(const bf16* Ah, const bf16* Al, int az,
                      const bf16* Bh, const bf16* Bl, int bz,
                      int Mtiles, int batch, int epi,
                      float* Cf, bf16* Ch, bf16* Cl, size_t sC, float alpha)
{
    dim3 grid(SEQ / 128, Mtiles, batch);
    if (epi == 0)
        hgemm3<0><<<grid, 256, SMEM_HG>>>(Ah, Al, Bh, Bl, Cf, Ch, Cl,
                                          SEQ, SEQ, sC, az, bz, alpha);
    else
        hgemm3<1><<<grid, 256, SMEM_HG>>>(Ah, Al, Bh, Bl, Cf, Ch, Cl,
                                          SEQ, SEQ, sC, az, bz, alpha);
}

extern "C" void kernel_launch(void* const* d_in, const int* in_sizes, int n_in,
                              void* d_out, int out_size)
{
    (void)in_sizes; (void)n_in; (void)out_size;
    const float* x = (const float*)d_in[0];
    const float* W[7] = { (const float*)d_in[1], (const float*)d_in[2],
                          (const float*)d_in[3], (const float*)d_in[4],
                          (const float*)d_in[5], (const float*)d_in[6],
                          (const float*)d_in[7] };
    float* out = (float*)d_out;

    cudaFuncSetAttribute((const void*)hgemm3<0>,
                         cudaFuncAttributeMaxDynamicSharedMemorySize, SMEM_HG);
    cudaFuncSetAttribute((const void*)hgemm3<1>,
                         cudaFuncAttributeMaxDynamicSharedMemorySize, SMEM_HG);

    bf16 *xh = sym_addr(g_xh), *xl = sym_addr(g_xl);
    bf16 *Wh = sym_addr(g_Wh), *Wl = sym_addr(g_Wl);
    bf16 *Q1h = sym_addr(g_Q1h), *Q1l = sym_addr(g_Q1l);
    bf16 *K1h = sym_addr(g_K1h), *K1l = sym_addr(g_K1l);
    bf16 *Q2h = sym_addr(g_Q2h), *Q2l = sym_addr(g_Q2l);
    bf16 *K2h = sym_addr(g_K2h), *K2l = sym_addr(g_K2l);
    bf16 *Vth = sym_addr(g_Vth), *Vtl = sym_addr(g_Vtl);
    bf16 *A1h = sym_addr(g_A1h), *A1l = sym_addr(g_A1l);
    bf16 *A2h = sym_addr(g_A2h), *A2l = sym_addr(g_A2l);
    bf16 *Chh = sym_addr(g_Ch),  *Cll = sym_addr(g_Cl);
    float *S1 = sym_addr(g_S1),  *S2 = sym_addr(g_S2);

    const size_t NTOT = (size_t)MROWS * SEQ;
    const float scale = 1.0f / sqrtf((float)SEQ);

    // 0) fp32 -> bf16 hi/lo
    f32_to_pair<<<2048, 256>>>(x, xh, xl, NTOT);
    for (int i = 0; i < 7; i++)
        f32_to_pair<<<512, 256>>>(W[i], Wh + (size_t)i * SSZ, Wl + (size_t)i * SSZ, SSZ);

    // 1) projections: P = X @ W^T  (M=16384) -> bf16 pairs
    run_hgemm(xh, xl, 0, Wh + 0 * SSZ, Wl + 0 * SSZ, 0, MROWS / 128, 1, 1,
              nullptr, Q1h, Q1l, 0, 1.0f);
    run_hgemm(xh, xl, 0, Wh + 1 * SSZ, Wl + 1 * SSZ, 0, MROWS / 128, 1, 1,
              nullptr, K1h, K1l, 0, 1.0f);
    run_hgemm(xh, xl, 0, Wh + 2 * SSZ, Wl + 2 * SSZ, 0, MROWS / 128, 1, 1,
              nullptr, Q2h, Q2l, 0, 1.0f);
    run_hgemm(xh, xl, 0, Wh + 3 * SSZ, Wl + 3 * SSZ, 0, MROWS / 128, 1, 1,
              nullptr, K2h, K2l, 0, 1.0f);

    // 2) Vt[h] = Wv @ X[h]^T  -> bf16 pair  (A = Wv, az=0; B = x, bz=SEQ)
    run_hgemm(Wh + 4 * SSZ, Wl + 4 * SSZ, 0, xh, xl, SEQ, SEQ / 128, NH, 1,
              nullptr, Vth, Vtl, SSZ, 1.0f);

    // 3) logits: S_i = scale * Q_i[h] @ K_i[h]^T  -> fp32
    run_hgemm(Q1h, Q1l, SEQ, K1h, K1l, SEQ, SEQ / 128, NH, 0,
              S1, nullptr, nullptr, SSZ, scale);
    run_hgemm(Q2h, Q2l, SEQ, K2h, K2l, SEQ, SEQ / 128, NH, 0,
              S2, nullptr, nullptr, SSZ, scale);

    // 4) softmax rows -> bf16 pairs
    softmax_pair<<<MROWS, 256>>>(S1, A1h, A1l);
    softmax_pair<<<MROWS, 256>>>(S2, A2h, A2l);

    // 5) scores: Sc_i = A_i @ W_i^T -> fp32 (reuse S1/S2)
    run_hgemm(A1h, A1l, SEQ, Wh + 5 * SSZ, Wl + 5 * SSZ, 0, SEQ / 128, NH, 0,
              S1, nullptr, nullptr, SSZ, 1.0f);
    run_hgemm(A2h, A2l, SEQ, Wh + 6 * SSZ, Wl + 6 * SSZ, 0, SEQ / 128, NH, 0,
              S2, nullptr, nullptr, SSZ, 1.0f);

    // 6) circle = (Sc1 - Sc2)^2 -> bf16 pair
    diffsq_pair<<<2048, 256>>>(S1, S2, Chh, Cll, NTOT);

    // 7) out[h] = circle[h] @ Vt[h]^T -> fp32
    run_hgemm(Chh, Cll, SEQ, Vth, Vtl, SEQ, SEQ / 128, NH, 0,
              out, nullptr, nullptr, SSZ, 1.0f);
}

// round 5
// speedup vs baseline: 1.7768x; 1.0878x over previous
#include <cuda_runtime.h>
#include <cuda_bf16.h>
#include <math.h>
#include <stdint.h>
#include <stddef.h>

// ============================================================================
// biSoftmax on GB300 via HMMA (mma.sync bf16) split-precision GEMMs.
// R5: 2-stage pipeline + 2 CTAs/SM; per-mi A-fragment loading to cut live regs;
//     all fp32->bf16-pair conversions fused into one launch (also makes
//     launch #6 a GEMM so ncu -s 5 profiles it).
// All GEMMs are NT: C[m,n] = alpha * sum_k A[m,k] * B[n,k]
// fp32 operands stored as bf16 (hi,lo); accumulate Ahi*Bhi + Ahi*Blo + Alo*Bhi.
// ============================================================================

#define SEQ 2048
#define NH 8
#define MROWS (NH * SEQ)                 // 16384
#define SSZ ((size_t)SEQ * SEQ)          // 2^22

typedef __nv_bfloat16 bf16;

// ---------------- scratch (device globals, allocation-free) ----------------
__device__ bf16 g_xh[(size_t)MROWS * SEQ],  g_xl[(size_t)MROWS * SEQ];
__device__ bf16 g_Wh[7 * SSZ],              g_Wl[7 * SSZ];
__device__ bf16 g_Q1h[(size_t)MROWS * SEQ], g_Q1l[(size_t)MROWS * SEQ];
__device__ bf16 g_K1h[(size_t)MROWS * SEQ], g_K1l[(size_t)MROWS * SEQ];
__device__ bf16 g_Q2h[(size_t)MROWS * SEQ], g_Q2l[(size_t)MROWS * SEQ];
__device__ bf16 g_K2h[(size_t)MROWS * SEQ], g_K2l[(size_t)MROWS * SEQ];
__device__ bf16 g_Vth[(size_t)MROWS * SEQ], g_Vtl[(size_t)MROWS * SEQ];
__device__ bf16 g_A1h[(size_t)MROWS * SEQ], g_A1l[(size_t)MROWS * SEQ];
__device__ bf16 g_A2h[(size_t)MROWS * SEQ], g_A2l[(size_t)MROWS * SEQ];
__device__ bf16 g_Ch [(size_t)MROWS * SEQ], g_Cl [(size_t)MROWS * SEQ];
__device__ float g_S1[(size_t)MROWS * SEQ], g_S2[(size_t)MROWS * SEQ];

// ---------------- PTX helpers ----------------
__device__ __forceinline__ uint32_t smem_u32(const void* p) {
    uint32_t a;
    asm("{ .reg .u64 t; cvta.to.shared.u64 t, %1; cvt.u32.u64 %0, t; }" : "=r"(a) : "l"(p));
    return a;
}

#define CP16(dst, src) \
    asm volatile("cp.async.cg.shared.global [%0], [%1], 16;" :: "r"(dst), "l"(src) : "memory")
#define CP_COMMIT() asm volatile("cp.async.commit_group;" ::: "memory")
#define CP_WAIT1()  asm volatile("cp.async.wait_group 1;" ::: "memory")

#define LDSM4(r0, r1, r2, r3, a) \
    asm volatile("ldmatrix.sync.aligned.m8n8.x4.shared.b16 {%0,%1,%2,%3}, [%4];" \
        : "=r"(r0), "=r"(r1), "=r"(r2), "=r"(r3) : "r"(a))

#define MMA_BF16(d, a, b) \
    asm volatile("mma.sync.aligned.m16n8k16.row.col.f32.bf16.bf16.f32 " \
        "{%0,%1,%2,%3}, {%4,%5,%6,%7}, {%8,%9}, {%0,%1,%2,%3};" \
        : "+f"((d)[0]), "+f"((d)[1]), "+f"((d)[2]), "+f"((d)[3]) \
        : "r"((a)[0]), "r"((a)[1]), "r"((a)[2]), "r"((a)[3]), "r"((b)[0]), "r"((b)[1]))

// ---------------- HMMA split-precision GEMM ----------------
// CTA tile 128x128, BK=32, 2 stages, 2 CTAs/SM.
// smem row = 32 bf16 (64B) + 16B pad = 80B.
// Stage layout: Ahi[0,10240) Alo[10240,20480) Bhi[20480,30720) Blo[30720,40960)
static constexpr int STAGE_B = 40960;
static constexpr int SMEM_HG = 2 * STAGE_B;   // 81920 -> 2 CTAs/SM

// EPI: 0 = fp32 * alpha, 1 = bf16 (hi,lo) pair
template <int EPI>
__global__ __launch_bounds__(256, 2)
void hgemm3(const bf16* __restrict__ Ah, const bf16* __restrict__ Al,
            const bf16* __restrict__ Bh, const bf16* __restrict__ Bl,
            float* __restrict__ Cf, bf16* __restrict__ Ch, bf16* __restrict__ Cl,
            int K, int ldc, size_t sC, int azRows, int bzRows, float alpha)
{
    extern __shared__ char smem[];
    const uint32_t sbase = smem_u32(smem);
    const int tid  = threadIdx.x;
    const int lane = tid & 31;
    const int wid  = tid >> 5;
    const int wm   = wid >> 2;          // 0..1  -> 64-row slab
    const int wn   = wid & 3;           // 0..3  -> 32-col slab
    const int row0 = blockIdx.y * 128;
    const int col0 = blockIdx.x * 128;
    const int z    = blockIdx.z;

    // ---- loader lanes ----
    const int lr  = tid >> 1;
    const int lcb = (tid & 1) * 2;
    const size_t arow = (size_t)(row0 + z * azRows + lr);
    const size_t brow = (size_t)(col0 + z * bzRows + lr);
    const bf16* pAh = Ah + arow * K + lcb * 8;
    const bf16* pAl = Al + arow * K + lcb * 8;
    const bf16* pBh = Bh + brow * K + lcb * 8;
    const bf16* pBl = Bl + brow * K + lcb * 8;
    const uint32_t lsw = (uint32_t)(lr & 3);
    const uint32_t st1 = lr * 80 + (((uint32_t)lcb ^ lsw) << 4);
    const uint32_t st2 = lr * 80 + ((((uint32_t)lcb + 1u) ^ lsw) << 4);

    auto prefetch = [&](int kt) {
        const uint32_t sb = sbase + (uint32_t)(kt & 1) * STAGE_B;
        const int go = kt * 32;
        CP16(sb +          st1, pAh + go); CP16(sb +          st2, pAh + go + 8);
        CP16(sb + 10240u + st1, pAl + go); CP16(sb + 10240u + st2, pAl + go + 8);
        CP16(sb + 20480u + st1, pBh + go); CP16(sb + 20480u + st2, pBh + go + 8);
        CP16(sb + 30720u + st1, pBl + go); CP16(sb + 30720u + st2, pBl + go + 8);
    };

    // ---- fragment addressing ----
    const int lr16  = lane & 15;
    const uint32_t khalf = (uint32_t)(lane >> 4);
    const uint32_t fsw   = (uint32_t)(lane & 3);
    uint32_t a_base[4], b_base[2];
    #pragma unroll
    for (int mi = 0; mi < 4; mi++) a_base[mi] = (uint32_t)(wm * 64 + mi * 16 + lr16) * 80u;
    #pragma unroll
    for (int g = 0; g < 2; g++)    b_base[g]  = (uint32_t)(wn * 32 + g * 16 + lr16) * 80u;

    float acc[4][4][4];
    #pragma unroll
    for (int mi = 0; mi < 4; mi++)
        #pragma unroll
        for (int nj = 0; nj < 4; nj++)
            #pragma unroll
            for (int q = 0; q < 4; q++) acc[mi][nj][q] = 0.0f;

    const int nk = K >> 5;

    prefetch(0); CP_COMMIT();
    prefetch(1); CP_COMMIT();

    for (int kt = 0; kt < nk; kt++) {
        CP_WAIT1();
        __syncthreads();

        const uint32_t stg = sbase + (uint32_t)(kt & 1) * STAGE_B;
        #pragma unroll
        for (int ks = 0; ks < 2; ks++) {
            const uint32_t coff = ((((uint32_t)(ks * 2) + khalf) ^ fsw) << 4);
            // B fragments for this ks (16 regs live)
            uint32_t Bhi[4][2], Blo[4][2];
            #pragma unroll
            for (int g = 0; g < 2; g++) {
                uint32_t q0, q1, q2, q3;
                LDSM4(q0, q1, q2, q3, stg + 20480u + b_base[g] + coff);
                Bhi[2 * g][0] = q0;     Bhi[2 * g][1] = q2;
                Bhi[2 * g + 1][0] = q1; Bhi[2 * g + 1][1] = q3;
                LDSM4(q0, q1, q2, q3, stg + 30720u + b_base[g] + coff);
                Blo[2 * g][0] = q0;     Blo[2 * g][1] = q2;
                Blo[2 * g + 1][0] = q1; Blo[2 * g + 1][1] = q3;
            }
            // A fragments per mi (8 regs live at a time)
            #pragma unroll
            for (int mi = 0; mi < 4; mi++) {
                uint32_t Ahi[4], Alo[4];
                LDSM4(Ahi[0], Ahi[1], Ahi[2], Ahi[3], stg + a_base[mi] + coff);
                LDSM4(Alo[0], Alo[1], Alo[2], Alo[3], stg + 10240u + a_base[mi] + coff);
                #pragma unroll
                for (int nj = 0; nj < 4; nj++) MMA_BF16(acc[mi][nj], Ahi, Bhi[nj]);
                #pragma unroll
                for (int nj = 0; nj < 4; nj++) MMA_BF16(acc[mi][nj], Ahi, Blo[nj]);
                #pragma unroll
                for (int nj = 0; nj < 4; nj++) MMA_BF16(acc[mi][nj], Alo, Bhi[nj]);
            }
        }

        __syncthreads();
        if (kt + 2 < nk) prefetch(kt + 2);
        CP_COMMIT();
    }

    // ---- epilogue ----
    const size_t cb = (size_t)z * sC;
    #pragma unroll
    for (int mi = 0; mi < 4; mi++) {
        #pragma unroll
        for (int nj = 0; nj < 4; nj++) {
            const int rg = row0 + wm * 64 + mi * 16 + (lane >> 2);
            const int cg = col0 + wn * 32 + nj * 8 + (lane & 3) * 2;
            float d0 = acc[mi][nj][0] * alpha, d1 = acc[mi][nj][1] * alpha;
            float d2 = acc[mi][nj][2] * alpha, d3 = acc[mi][nj][3] * alpha;
            const size_t i0 = cb + (size_t)rg * ldc + cg;
            const size_t i1 = cb + (size_t)(rg + 8) * ldc + cg;
            if (EPI == 0) {
                *(float2*)(Cf + i0) = make_float2(d0, d1);
                *(float2*)(Cf + i1) = make_float2(d2, d3);
            } else {
                __nv_bfloat162 h, l;
                h.x = __float2bfloat16(d0);
                h.y = __float2bfloat16(d1);
                l.x = __float2bfloat16(d0 - __bfloat162float(h.x));
                l.y = __float2bfloat16(d1 - __bfloat162float(h.y));
                *(__nv_bfloat162*)(Ch + i0) = h;
                *(__nv_bfloat162*)(Cl + i0) = l;
                h.x = __float2bfloat16(d2);
                h.y = __float2bfloat16(d3);
                l.x = __float2bfloat16(d2 - __bfloat162float(h.x));
                l.y = __float2bfloat16(d3 - __bfloat162float(h.y));
                *(__nv_bfloat162*)(Ch + i1) = h;
                *(__nv_bfloat162*)(Cl + i1) = l;
            }
        }
    }
}

// ---------------- fused conversion: x + all 7 weights in ONE launch ----------
struct WPtrs { const float* p[7]; };

__global__ __launch_bounds__(256)
void convert_all(const float* __restrict__ x, WPtrs w,
                 bf16* __restrict__ xh, bf16* __restrict__ xl,
                 bf16* __restrict__ Wh, bf16* __restrict__ Wl)
{
    const size_t stride = (size_t)gridDim.x * blockDim.x;
    size_t i = (size_t)blockIdx.x * blockDim.x + threadIdx.x;
    if (blockIdx.y == 0) {
        const size_t n = (size_t)MROWS * SEQ;
        for (; i < n; i += stride) {
            float f = x[i];
            bf16 h = __float2bfloat16(f);
            xh[i] = h;
            xl[i] = __float2bfloat16(f - __bfloat162float(h));
        }
    } else {
        const size_t n = 7 * SSZ;
        for (; i < n; i += stride) {
            const int r = (int)(i >> 22);            // SSZ = 2^22
            const size_t off = i & (SSZ - 1);
            float f = w.p[r][off];
            bf16 h = __float2bfloat16(f);
            Wh[i] = h;
            Wl[i] = __float2bfloat16(f - __bfloat162float(h));
        }
    }
}

__global__ __launch_bounds__(256)
void softmax_pair(const float* __restrict__ S, bf16* __restrict__ Ph,
                  bf16* __restrict__ Pl)
{
    const int tid = threadIdx.x;
    const float* p = S + (size_t)blockIdx.x * SEQ;
    bf16* oh = Ph + (size_t)blockIdx.x * SEQ;
    bf16* ol = Pl + (size_t)blockIdx.x * SEQ;
    __shared__ float buf[SEQ];
    __shared__ float red[256];

    float m = -INFINITY;
    for (int i = tid; i < SEQ; i += 256) { float v = p[i]; buf[i] = v; m = fmaxf(m, v); }
    red[tid] = m; __syncthreads();
    for (int s = 128; s > 0; s >>= 1) { if (tid < s) red[tid] = fmaxf(red[tid], red[tid + s]); __syncthreads(); }
    m = red[0]; __syncthreads();

    float sum = 0.0f;
    for (int i = tid; i < SEQ; i += 256) { float e = __expf(buf[i] - m); buf[i] = e; sum += e; }
    red[tid] = sum; __syncthreads();
    for (int s = 128; s > 0; s >>= 1) { if (tid < s) red[tid] += red[tid + s]; __syncthreads(); }
    const float inv = 1.0f / red[0]; __syncthreads();

    for (int i = tid; i < SEQ; i += 256) {
        float f = buf[i] * inv;
        bf16 h = __float2bfloat16(f);
        oh[i] = h;
        ol[i] = __float2bfloat16(f - __bfloat162float(h));
    }
}

__global__ __launch_bounds__(256)
void diffsq_pair(const float* __restrict__ a, const float* __restrict__ b,
                 bf16* __restrict__ hi, bf16* __restrict__ lo, size_t n)
{
    size_t i = (size_t)blockIdx.x * blockDim.x + threadIdx.x;
    size_t st = (size_t)gridDim.x * blockDim.x;
    for (; i < n; i += st) {
        float d = a[i] - b[i];
        float f = d * d;
        bf16 h = __float2bfloat16(f);
        hi[i] = h;
        lo[i] = __float2bfloat16(f - __bfloat162float(h));
    }
}

// ---------------- host side ----------------
template <typename T>
static T* sym_addr(T* symbol) {
    void* p = nullptr;
    cudaGetSymbolAddress(&p, (const void*)symbol);
    return (T*)p;
}

static void run_hgemm(const bf16* Ah, const bf16* Al, int az,
                      const bf16* Bh, const bf16* Bl, int bz,
                      int Mtiles, int batch, int epi,
                      float* Cf, bf16* Ch, bf16* Cl, size_t sC, float alpha)
{
    dim3 grid(SEQ / 128, Mtiles, batch);
    if (epi == 0)
        hgemm3<0><<<grid, 256, SMEM_HG>>>(Ah, Al, Bh, Bl, Cf, Ch, Cl,
                                          SEQ, SEQ, sC, az, bz, alpha);
    else
        hgemm3<1><<<grid, 256, SMEM_HG>>>(Ah, Al, Bh, Bl, Cf, Ch, Cl,
                                          SEQ, SEQ, sC, az, bz, alpha);
}

extern "C" void kernel_launch(void* const* d_in, const int* in_sizes, int n_in,
                              void* d_out, int out_size)
{
    (void)in_sizes; (void)n_in; (void)out_size;
    const float* x = (const float*)d_in[0];
    WPtrs w;
    for (int i = 0; i < 7; i++) w.p[i] = (const float*)d_in[1 + i];
    float* out = (float*)d_out;

    cudaFuncSetAttribute((const void*)hgemm3<0>,
                         cudaFuncAttributeMaxDynamicSharedMemorySize, SMEM_HG);
    cudaFuncSetAttribute((const void*)hgemm3<1>,
                         cudaFuncAttributeMaxDynamicSharedMemorySize, SMEM_HG);

    bf16 *xh = sym_addr(g_xh), *xl = sym_addr(g_xl);
    bf16 *Wh = sym_addr(g_Wh), *Wl = sym_addr(g_Wl);
    bf16 *Q1h = sym_addr(g_Q1h), *Q1l = sym_addr(g_Q1l);
    bf16 *K1h = sym_addr(g_K1h), *K1l = sym_addr(g_K1l);
    bf16 *Q2h = sym_addr(g_Q2h), *Q2l = sym_addr(g_Q2l);
    bf16 *K2h = sym_addr(g_K2h), *K2l = sym_addr(g_K2l);
    bf16 *Vth = sym_addr(g_Vth), *Vtl = sym_addr(g_Vtl);
    bf16 *A1h = sym_addr(g_A1h), *A1l = sym_addr(g_A1l);
    bf16 *A2h = sym_addr(g_A2h), *A2l = sym_addr(g_A2l);
    bf16 *Chh = sym_addr(g_Ch),  *Cll = sym_addr(g_Cl);
    float *S1 = sym_addr(g_S1),  *S2 = sym_addr(g_S2);

    const size_t NTOT = (size_t)MROWS * SEQ;
    const float scale = 1.0f / sqrtf((float)SEQ);

    // [0] conversions (single launch)
    convert_all<<<dim3(1024, 2), 256>>>(x, w, xh, xl, Wh, Wl);

    // [1..4] projections: P = X @ W^T -> bf16 pairs
    run_hgemm(xh, xl, 0, Wh + 0 * SSZ, Wl + 0 * SSZ, 0, MROWS / 128, 1, 1,
              nullptr, Q1h, Q1l, 0, 1.0f);
    run_hgemm(xh, xl, 0, Wh + 1 * SSZ, Wl + 1 * SSZ, 0, MROWS / 128, 1, 1,
              nullptr, K1h, K1l, 0, 1.0f);
    run_hgemm(xh, xl, 0, Wh + 2 * SSZ, Wl + 2 * SSZ, 0, MROWS / 128, 1, 1,
              nullptr, Q2h, Q2l, 0, 1.0f);
    run_hgemm(xh, xl, 0, Wh + 3 * SSZ, Wl + 3 * SSZ, 0, MROWS / 128, 1, 1,
              nullptr, K2h, K2l, 0, 1.0f);

    // [5] Vt[h] = Wv @ X[h]^T -> bf16 pair   (this is the ncu -s 5 target)
    run_hgemm(Wh + 4 * SSZ, Wl + 4 * SSZ, 0, xh, xl, SEQ, SEQ / 128, NH, 1,
              nullptr, Vth, Vtl, SSZ, 1.0f);

    // [6,7] logits: S_i = scale * Q_i[h] @ K_i[h]^T -> fp32
    run_hgemm(Q1h, Q1l, SEQ, K1h, K1l, SEQ, SEQ / 128, NH, 0,
              S1, nullptr, nullptr, SSZ, scale);
    run_hgemm(Q2h, Q2l, SEQ, K2h, K2l, SEQ, SEQ / 128, NH, 0,
              S2, nullptr, nullptr, SSZ, scale);

    // [8,9] softmax rows -> bf16 pairs
    softmax_pair<<<MROWS, 256>>>(S1, A1h, A1l);
    softmax_pair<<<MROWS, 256>>>(S2, A2h, A2l);

    // [10,11] scores: Sc_i = A_i @ W_i^T -> fp32 (reuse S1/S2)
    run_hgemm(A1h, A1l, SEQ, Wh + 5 * SSZ, Wl + 5 * SSZ, 0, SEQ / 128, NH, 0,
              S1, nullptr, nullptr, SSZ, 1.0f);
    run_hgemm(A2h, A2l, SEQ, Wh + 6 * SSZ, Wl + 6 * SSZ, 0, SEQ / 128, NH, 0,
              S2, nullptr, nullptr, SSZ, 1.0f);

    // [12] circle = (Sc1 - Sc2)^2 -> bf16 pair
    diffsq_pair<<<2048, 256>>>(S1, S2, Chh, Cll, NTOT);

    // [13] out[h] = circle[h] @ Vt[h]^T -> fp32
    run_hgemm(Chh, Cll, SEQ, Vth, Vtl, SEQ, SEQ / 128, NH, 0,
              out, nullptr, nullptr, SSZ, 1.0f);
}